// round 6
// baseline (speedup 1.0000x reference)
#include <cuda_runtime.h>
#include <cuda_bf16.h>
#include <cstdint>

// ---------------------------------------------------------------------------
// BilateralRotation: out[b,c] = R1[c] @ wkv[b,c] @ R2[c]
//   R = Cayley(p) = (I - A)(I + A)^{-1} = (I + A)^{-1}(I - A)   (commute)
//
// Stage 1: cayley_kernel — register-resident GJ on [I+A | I-A], fully
//          unrolled (static reg indices), emits R directly.
// Stage 2: bilat_kernel — 4096 blocks, 128 thr, 4 CTAs/SM. All GEMM operand
//          fragments except T^T come straight from global (L1-hot R, one-
//          touch W) with inline tf32 rounding; only T^T lives in SMEM.
// ---------------------------------------------------------------------------

#define NUM_HEADS 32
#define DIM 64

__device__ float g_R1 [NUM_HEADS * DIM * DIM];   // R1 row-major [i][l]
__device__ float g_R2T[NUM_HEADS * DIM * DIM];   // R2 transposed [n][k]

__device__ __forceinline__ float tf32r(float x) {
    uint32_t u;
    asm("cvt.rna.tf32.f32 %0, %1;" : "=r"(u) : "f"(x));
    return __uint_as_float(u);
}

__device__ __forceinline__ void pbar(int id) {
    asm volatile("bar.sync %0, 64;" :: "r"(id) : "memory");
}

// ---------------------------------------------------------------------------
// Stage 1: Cayley. One block per (side, head), 256 threads.
// Thread (r = tid>>2, q = tid&3) owns 16 cols of row r of [M | X] where
// M = I + A, X = I - A, register resident. Fully unrolled k-loop keeps all
// register indices static (no local-memory demotion). Unpivoted GJ is safe:
// symmetric part of I+A is I (SPD). At the end X = (I+A)^{-1}(I-A) = R.
// ---------------------------------------------------------------------------
__global__ __launch_bounds__(256) void cayley_kernel(
    const float* __restrict__ pL, const float* __restrict__ pR)
{
    const int side = blockIdx.x >> 5;
    const int h    = blockIdx.x & 31;
    const float* p = (side ? pR : pL) + h * DIM * DIM;

    const int tid = threadIdx.x;
    const int r   = tid >> 2;
    const int q   = tid & 3;
    const int cb  = q * 16;

    __shared__ float rowM[DIM], rowX[DIM], colM[DIM];

    float m[16], x[16];
    #pragma unroll
    for (int j = 0; j < 16; j++) {
        int c = cb + j;
        float a = 0.5f * (p[r * DIM + c] - p[c * DIM + r]);
        float id = (r == c) ? 1.0f : 0.0f;
        m[j] = id + a;
        x[j] = id - a;
    }
    __syncthreads();

    #pragma unroll
    for (int k = 0; k < DIM; k++) {
        if (r == k) {
            #pragma unroll
            for (int j = 0; j < 16; j++) { rowM[cb + j] = m[j]; rowX[cb + j] = x[j]; }
        }
        if ((k >> 4) == q) colM[r] = m[k & 15];   // static index (k is literal)
        __syncthreads();

        const float invp = 1.0f / rowM[k];
        if (r == k) {
            #pragma unroll
            for (int j = 0; j < 16; j++) { m[j] *= invp; x[j] *= invp; }
        } else {
            const float f = colM[r] * invp;
            #pragma unroll
            for (int j = 0; j < 16; j++) {
                m[j] -= f * rowM[cb + j];
                x[j] -= f * rowX[cb + j];
            }
        }
        __syncthreads();
    }

    // x[] now holds R[r][cb..cb+15]
    if (side == 0) {
        float* dst = g_R1 + h * DIM * DIM;
        #pragma unroll
        for (int j = 0; j < 16; j++) dst[r * DIM + cb + j] = x[j];
    } else {
        float* dst = g_R2T + h * DIM * DIM;
        #pragma unroll
        for (int j = 0; j < 16; j++) dst[(cb + j) * DIM + r] = x[j];
    }
}

// ---------------------------------------------------------------------------
// Stage 2: bilateral rotation.
// Per block: 2 warp-pairs x 2 passes = 4 batches (same head).
// GEMM1: T = W @ R2   — A frags LDG from wkv (one-touch), B frags LDG from
//                        g_R2T (L1-hot), both inline tf32-rounded.
//         T^T stored swizzled into SMEM (rounded).
// GEMM2: out = R1 @ T — A frags LDG from g_R1 (L1-hot, inline rounded),
//                        B frags LDS from SMEM T^T.
// SMEM swizzle: elem (row, col) at [row*64 + (col ^ (4*(row&7)))].
// ---------------------------------------------------------------------------
__global__ __launch_bounds__(128, 4) void bilat_kernel(
    const float* __restrict__ wkv, float* __restrict__ out)
{
    __shared__ float sT2[2][DIM * DIM];   // per-pair T^T buffers (32 KB)

    const int blk  = blockIdx.x;
    const int head = blk >> 7;            // head-major: R matrices L1/L2-hot
    const int g    = blk & 127;

    const int tid    = threadIdx.x;
    const int lane   = tid & 31;
    const int warp   = tid >> 5;
    const int pairid = warp >> 1;         // 0,1
    const int w2     = warp & 1;
    const int grp    = lane >> 2;         // 0..7
    const int tig    = lane & 3;          // 0..3
    const int base   = w2 * 32;

    float* sT = sT2[pairid];
    const float* r1p = g_R1  + (size_t)head * (DIM * DIM);
    const float* r2p = g_R2T + (size_t)head * (DIM * DIM);

    #pragma unroll 1
    for (int pass = 0; pass < 2; pass++) {
        const int b = g * 4 + pass * 2 + pairid;
        const float* wA = wkv + (size_t)(b * NUM_HEADS + head) * (DIM * DIM);

        if (pass) pbar(1 + pairid);       // prior GEMM2 done reading sT

        // ---- GEMM1: T = W @ R2 ----
        float acc[2][8][4];
        #pragma unroll
        for (int mt = 0; mt < 2; mt++)
            #pragma unroll
            for (int nt = 0; nt < 8; nt++)
                { acc[mt][nt][0]=0.f; acc[mt][nt][1]=0.f; acc[mt][nt][2]=0.f; acc[mt][nt][3]=0.f; }

        #pragma unroll
        for (int kb = 0; kb < DIM; kb += 8) {
            uint32_t a[2][4];
            #pragma unroll
            for (int mt = 0; mt < 2; mt++) {
                const int r0 = base + mt * 16 + grp;
                a[mt][0] = __float_as_uint(tf32r(wA[ r0      * DIM + kb + tig    ]));
                a[mt][1] = __float_as_uint(tf32r(wA[(r0 + 8) * DIM + kb + tig    ]));
                a[mt][2] = __float_as_uint(tf32r(wA[ r0      * DIM + kb + tig + 4]));
                a[mt][3] = __float_as_uint(tf32r(wA[(r0 + 8) * DIM + kb + tig + 4]));
            }
            #pragma unroll
            for (int nt = 0; nt < 8; nt++) {
                const int n = nt * 8 + grp;
                uint32_t b0 = __float_as_uint(tf32r(r2p[n * DIM + kb + tig    ]));
                uint32_t b1 = __float_as_uint(tf32r(r2p[n * DIM + kb + tig + 4]));
                #pragma unroll
                for (int mt = 0; mt < 2; mt++) {
                    asm volatile(
                        "mma.sync.aligned.m16n8k8.row.col.f32.tf32.tf32.f32 "
                        "{%0,%1,%2,%3}, {%4,%5,%6,%7}, {%8,%9}, {%0,%1,%2,%3};\n"
                        : "+f"(acc[mt][nt][0]), "+f"(acc[mt][nt][1]),
                          "+f"(acc[mt][nt][2]), "+f"(acc[mt][nt][3])
                        : "r"(a[mt][0]), "r"(a[mt][1]), "r"(a[mt][2]), "r"(a[mt][3]),
                          "r"(b0), "r"(b1));
                }
            }
        }

        // ---- store T^T (swizzled, tf32-rounded) ----
        #pragma unroll
        for (int mt = 0; mt < 2; mt++) {
            const int r0 = base + mt * 16 + grp;
            #pragma unroll
            for (int nt = 0; nt < 8; nt++) {
                const int c0 = nt * 8 + 2 * tig;
                const int c1 = c0 + 1;
                sT[c0 * DIM + ( r0      ^ ((c0 & 7) << 2))] = tf32r(acc[mt][nt][0]);
                sT[c1 * DIM + ( r0      ^ ((c1 & 7) << 2))] = tf32r(acc[mt][nt][1]);
                sT[c0 * DIM + ((r0 + 8) ^ ((c0 & 7) << 2))] = tf32r(acc[mt][nt][2]);
                sT[c1 * DIM + ((r0 + 8) ^ ((c1 & 7) << 2))] = tf32r(acc[mt][nt][3]);
            }
        }
        pbar(1 + pairid);                 // T^T visible to the pair

        // ---- GEMM2: out = R1 @ T ----
        #pragma unroll
        for (int mt = 0; mt < 2; mt++)
            #pragma unroll
            for (int nt = 0; nt < 8; nt++)
                { acc[mt][nt][0]=0.f; acc[mt][nt][1]=0.f; acc[mt][nt][2]=0.f; acc[mt][nt][3]=0.f; }

        #pragma unroll
        for (int kb = 0; kb < DIM; kb += 8) {
            const int cx0 = (kb + tig)     ^ (grp << 2);
            const int cx4 = (kb + tig + 4) ^ (grp << 2);
            uint32_t a[2][4];
            #pragma unroll
            for (int mt = 0; mt < 2; mt++) {
                const int r0 = base + mt * 16 + grp;
                a[mt][0] = __float_as_uint(tf32r(r1p[ r0      * DIM + kb + tig    ]));
                a[mt][1] = __float_as_uint(tf32r(r1p[(r0 + 8) * DIM + kb + tig    ]));
                a[mt][2] = __float_as_uint(tf32r(r1p[ r0      * DIM + kb + tig + 4]));
                a[mt][3] = __float_as_uint(tf32r(r1p[(r0 + 8) * DIM + kb + tig + 4]));
            }
            #pragma unroll
            for (int nt = 0; nt < 8; nt++) {
                const int n = nt * 8 + grp;
                uint32_t b0 = __float_as_uint(sT[n * DIM + cx0]);
                uint32_t b1 = __float_as_uint(sT[n * DIM + cx4]);
                #pragma unroll
                for (int mt = 0; mt < 2; mt++) {
                    asm volatile(
                        "mma.sync.aligned.m16n8k8.row.col.f32.tf32.tf32.f32 "
                        "{%0,%1,%2,%3}, {%4,%5,%6,%7}, {%8,%9}, {%0,%1,%2,%3};\n"
                        : "+f"(acc[mt][nt][0]), "+f"(acc[mt][nt][1]),
                          "+f"(acc[mt][nt][2]), "+f"(acc[mt][nt][3])
                        : "r"(a[mt][0]), "r"(a[mt][1]), "r"(a[mt][2]), "r"(a[mt][3]),
                          "r"(b0), "r"(b1));
                }
            }
        }

        // ---- epilogue: coalesced float2 stores ----
        float* dst = out + (size_t)(b * NUM_HEADS + head) * (DIM * DIM);
        #pragma unroll
        for (int mt = 0; mt < 2; mt++) {
            const int r0 = base + mt * 16 + grp;
            #pragma unroll
            for (int nt = 0; nt < 8; nt++) {
                const int col = nt * 8 + 2 * tig;
                *reinterpret_cast<float2*>(dst +  r0      * DIM + col) =
                    make_float2(acc[mt][nt][0], acc[mt][nt][1]);
                *reinterpret_cast<float2*>(dst + (r0 + 8) * DIM + col) =
                    make_float2(acc[mt][nt][2], acc[mt][nt][3]);
            }
        }
    }
}

// ---------------------------------------------------------------------------
extern "C" void kernel_launch(void* const* d_in, const int* in_sizes, int n_in,
                              void* d_out, int out_size)
{
    const float* wkv = (const float*)d_in[0];
    const float* pL  = (const float*)d_in[1];
    const float* pR  = (const float*)d_in[2];
    float* out       = (float*)d_out;

    cayley_kernel<<<2 * NUM_HEADS, 256>>>(pL, pR);
    bilat_kernel<<<NUM_HEADS * 128, 128>>>(wkv, out);
}

// round 7
// speedup vs baseline: 1.7424x; 1.7424x over previous
#include <cuda_runtime.h>
#include <cuda_bf16.h>
#include <cstdint>

// ---------------------------------------------------------------------------
// BilateralRotation: out[b,c] = R1[c] @ wkv[b,c] @ R2[c]
//   R = Cayley(p) = (I - A)(I + A)^{-1} = (I + A)^{-1}(I - A)
//
// Stage 1: cayley_kernel — register-resident GJ on [I+A | I-A] -> R directly.
// Stage 2: bilat_kernel — 2048 blocks (head-major), 128 thr, 3 CTAs/SM,
//          cp.async staging, tf32 mma.sync with 64-bit fragment LDS via
//          k-relabel (logical cols (kb+tig, kb+tig+4) -> physical
//          (kb+2tig, kb+2tig+1); same bijection on both operands => product
//          unchanged). Pitch 72: pair-bank = 4*grp + tig (conflict-free).
// ---------------------------------------------------------------------------

#define NUM_HEADS 32
#define DIM 64
#define PITCH 72                         // floats per row; pair-bank conflict-free
#define MATP (DIM * PITCH)               // 4608 floats = 18432 B per buffer
#define SMEM_TOTAL_BYTES (4 * MATP * 4)  // sR1, sR2T, sW0, sW1 = 73728 B

__device__ float g_R1 [NUM_HEADS * DIM * DIM];   // R1 row-major [i][l]
__device__ float g_R2T[NUM_HEADS * DIM * DIM];   // R2 transposed [n][k]

__device__ __forceinline__ float tf32r(float x) {
    uint32_t u;
    asm("cvt.rna.tf32.f32 %0, %1;" : "=r"(u) : "f"(x));
    return __uint_as_float(u);
}

__device__ __forceinline__ void cp16(float* dst_smem, const void* src) {
    uint32_t d = (uint32_t)__cvta_generic_to_shared(dst_smem);
    asm volatile("cp.async.ca.shared.global [%0], [%1], 16;\n" :: "r"(d), "l"(src));
}
#define CP_COMMIT() asm volatile("cp.async.commit_group;\n")
#define CP_WAIT0()  asm volatile("cp.async.wait_group 0;\n" ::: "memory")
#define CP_WAIT1()  asm volatile("cp.async.wait_group 1;\n" ::: "memory")

__device__ __forceinline__ void pbar(int id) {
    asm volatile("bar.sync %0, 64;" :: "r"(id) : "memory");
}

// ---------------------------------------------------------------------------
// Stage 1: Cayley. One block per (side, head), 256 threads.
// Thread (r = tid>>2, q = tid&3) owns 16 cols of row r of [M | X],
// M = I + A, X = I - A, register resident, fully unrolled k-loop.
// Unpivoted GJ safe: symmetric part of I+A is I (SPD). End: X = R.
// ---------------------------------------------------------------------------
__global__ __launch_bounds__(256) void cayley_kernel(
    const float* __restrict__ pL, const float* __restrict__ pR)
{
    const int side = blockIdx.x >> 5;
    const int h    = blockIdx.x & 31;
    const float* p = (side ? pR : pL) + h * DIM * DIM;

    const int tid = threadIdx.x;
    const int r   = tid >> 2;
    const int q   = tid & 3;
    const int cb  = q * 16;

    __shared__ float rowM[DIM], rowX[DIM], colM[DIM];

    float m[16], x[16];
    #pragma unroll
    for (int j = 0; j < 16; j++) {
        int c = cb + j;
        float a = 0.5f * (p[r * DIM + c] - p[c * DIM + r]);
        float id = (r == c) ? 1.0f : 0.0f;
        m[j] = id + a;
        x[j] = id - a;
    }
    __syncthreads();

    #pragma unroll
    for (int k = 0; k < DIM; k++) {
        if (r == k) {
            #pragma unroll
            for (int j = 0; j < 16; j++) { rowM[cb + j] = m[j]; rowX[cb + j] = x[j]; }
        }
        if ((k >> 4) == q) colM[r] = m[k & 15];   // k literal -> static index
        __syncthreads();

        const float invp = 1.0f / rowM[k];
        if (r == k) {
            #pragma unroll
            for (int j = 0; j < 16; j++) { m[j] *= invp; x[j] *= invp; }
        } else {
            const float f = colM[r] * invp;
            #pragma unroll
            for (int j = 0; j < 16; j++) {
                m[j] -= f * rowM[cb + j];
                x[j] -= f * rowX[cb + j];
            }
        }
        __syncthreads();
    }

    if (side == 0) {
        float* dst = g_R1 + h * DIM * DIM;
        #pragma unroll
        for (int j = 0; j < 16; j++) dst[r * DIM + cb + j] = x[j];
    } else {
        float* dst = g_R2T + h * DIM * DIM;
        #pragma unroll
        for (int j = 0; j < 16; j++) dst[(cb + j) * DIM + r] = x[j];
    }
}

// ---------------------------------------------------------------------------
// Stage 2 GEMM core: 32x64 warp tile, float2 fragment loads (k-relabeled).
// ---------------------------------------------------------------------------
template<bool CVTA>
__device__ __forceinline__ void gemm32x64(
    const float* __restrict__ Am,   // A [m][k], pitch PITCH; rows base..base+31
    const float* __restrict__ Bm,   // B [n][k], pitch PITCH
    float acc[2][8][4], int base, int grp, int tig)
{
    #pragma unroll
    for (int kb = 0; kb < DIM; kb += 8) {
        const int kc = kb + 2 * tig;           // physical col pair start
        uint32_t a[2][4];
        #pragma unroll
        for (int mt = 0; mt < 2; mt++) {
            const int r0 = base + mt * 16 + grp;
            float2 va = *reinterpret_cast<const float2*>(&Am[ r0      * PITCH + kc]);
            float2 vb = *reinterpret_cast<const float2*>(&Am[(r0 + 8) * PITCH + kc]);
            if (CVTA) {
                va.x = tf32r(va.x); va.y = tf32r(va.y);
                vb.x = tf32r(vb.x); vb.y = tf32r(vb.y);
            }
            a[mt][0] = __float_as_uint(va.x);  // logical col kb+tig
            a[mt][1] = __float_as_uint(vb.x);
            a[mt][2] = __float_as_uint(va.y);  // logical col kb+tig+4
            a[mt][3] = __float_as_uint(vb.y);
        }
        #pragma unroll
        for (int nt = 0; nt < 8; nt++) {
            const int n = nt * 8 + grp;
            float2 v = *reinterpret_cast<const float2*>(&Bm[n * PITCH + kc]);
            uint32_t b0 = __float_as_uint(v.x);
            uint32_t b1 = __float_as_uint(v.y);
            #pragma unroll
            for (int mt = 0; mt < 2; mt++) {
                asm volatile(
                    "mma.sync.aligned.m16n8k8.row.col.f32.tf32.tf32.f32 "
                    "{%0,%1,%2,%3}, {%4,%5,%6,%7}, {%8,%9}, {%0,%1,%2,%3};\n"
                    : "+f"(acc[mt][nt][0]), "+f"(acc[mt][nt][1]),
                      "+f"(acc[mt][nt][2]), "+f"(acc[mt][nt][3])
                    : "r"(a[mt][0]), "r"(a[mt][1]), "r"(a[mt][2]), "r"(a[mt][3]),
                      "r"(b0), "r"(b1));
            }
        }
    }
}

// ---------------------------------------------------------------------------
// Stage 2: 2048 blocks (head-major), 128 threads = 2 warp-pairs, 4 passes
// -> 8 batches/block sharing one R staging. Single W/T buffer per pair.
// ---------------------------------------------------------------------------
__global__ __launch_bounds__(128, 3) void bilat_kernel(
    const float* __restrict__ wkv, float* __restrict__ out)
{
    extern __shared__ float smem[];
    float* sR1  = smem;                  // A of GEMM2 (pre-rounded)
    float* sR2T = smem + MATP;           // B of GEMM1 (pre-rounded)

    const int blk  = blockIdx.x;
    const int head = blk >> 6;           // head-major: R matrices L2-hot
    const int g    = blk & 63;

    const int tid    = threadIdx.x;
    const int lane   = tid & 31;
    const int warp   = tid >> 5;
    const int pairid = warp >> 1;        // 0,1
    const int w2     = warp & 1;
    const int grp    = lane >> 2;        // 0..7
    const int tig    = lane & 3;         // 0..3
    const int base   = w2 * 32;
    const int tp     = tid & 63;

    float* sW = smem + 2 * MATP + pairid * MATP;

    // ---- cp.async: R1 + R2T (raw), group 0 ----
    {
        const float4* r1g = reinterpret_cast<const float4*>(g_R1)  + (size_t)head * 1024;
        const float4* r2g = reinterpret_cast<const float4*>(g_R2T) + (size_t)head * 1024;
        #pragma unroll 4
        for (int ci = tid; ci < 1024; ci += 128) {
            int r = ci >> 4, c4 = (ci & 15) << 2;
            cp16(&sR1 [r * PITCH + c4], r1g + ci);
            cp16(&sR2T[r * PITCH + c4], r2g + ci);
        }
    }
    CP_COMMIT();

    // ---- cp.async: W for pass 0 (raw), group 1 ----
    {
        const int b0 = g * 8 + pairid;
        const float4* wsrc = reinterpret_cast<const float4*>(wkv)
                           + (size_t)(b0 * NUM_HEADS + head) * 1024;
        #pragma unroll 4
        for (int ci = tp; ci < 1024; ci += 64) {
            int r = ci >> 4, c4 = (ci & 15) << 2;
            cp16(&sW[r * PITCH + c4], wsrc + ci);
        }
    }
    CP_COMMIT();

    // ---- R arrived: in-place tf32 rounding (covers both R buffers) ----
    CP_WAIT1();
    __syncthreads();
    {
        float4* rp = reinterpret_cast<float4*>(smem);   // 2*MATP floats
        #pragma unroll 4
        for (int i = tid; i < (2 * MATP) / 4; i += 128) {
            float4 v = rp[i];
            v.x = tf32r(v.x); v.y = tf32r(v.y); v.z = tf32r(v.z); v.w = tf32r(v.w);
            rp[i] = v;
        }
    }
    __syncthreads();

    #pragma unroll 1
    for (int pass = 0; pass < 4; pass++) {
        const int b = g * 8 + pass * 2 + pairid;

        CP_WAIT0();            // this pass's W chunks (own thread) done
        pbar(1 + pairid);      // all pair threads' chunks visible

        // ---- GEMM1: T = W @ R2  (A = raw W, inline cvt; B = sR2T) ----
        float acc[2][8][4];
        #pragma unroll
        for (int mt = 0; mt < 2; mt++)
            #pragma unroll
            for (int nt = 0; nt < 8; nt++)
                { acc[mt][nt][0]=0.f; acc[mt][nt][1]=0.f; acc[mt][nt][2]=0.f; acc[mt][nt][3]=0.f; }
        gemm32x64<true>(sW, sR2T, acc, base, grp, tig);
        pbar(1 + pairid);      // pair done reading W

        // ---- write T^T into sW ([col][row], tf32-rounded) ----
        #pragma unroll
        for (int mt = 0; mt < 2; mt++) {
            const int r0 = base + mt * 16 + grp;
            #pragma unroll
            for (int nt = 0; nt < 8; nt++) {
                const int c0 = nt * 8 + 2 * tig;
                sW[ c0      * PITCH + r0    ] = tf32r(acc[mt][nt][0]);
                sW[(c0 + 1) * PITCH + r0    ] = tf32r(acc[mt][nt][1]);
                sW[ c0      * PITCH + r0 + 8] = tf32r(acc[mt][nt][2]);
                sW[(c0 + 1) * PITCH + r0 + 8] = tf32r(acc[mt][nt][3]);
            }
        }
        pbar(1 + pairid);      // T^T visible to the pair

        // ---- GEMM2: out = R1 @ T  (A = sR1, B = T^T in sW) ----
        #pragma unroll
        for (int mt = 0; mt < 2; mt++)
            #pragma unroll
            for (int nt = 0; nt < 8; nt++)
                { acc[mt][nt][0]=0.f; acc[mt][nt][1]=0.f; acc[mt][nt][2]=0.f; acc[mt][nt][3]=0.f; }
        gemm32x64<false>(sR1, sW, acc, base, grp, tig);
        pbar(1 + pairid);      // sW free

        // ---- prefetch next pass's W (overlaps epilogue stores) ----
        if (pass < 3) {
            const int bn = b + 2;
            const float4* wsrc = reinterpret_cast<const float4*>(wkv)
                               + (size_t)(bn * NUM_HEADS + head) * 1024;
            #pragma unroll 4
            for (int ci = tp; ci < 1024; ci += 64) {
                int r = ci >> 4, c4 = (ci & 15) << 2;
                cp16(&sW[r * PITCH + c4], wsrc + ci);
            }
            CP_COMMIT();
        }

        // ---- epilogue: coalesced float2 stores ----
        float* dst = out + (size_t)(b * NUM_HEADS + head) * (DIM * DIM);
        #pragma unroll
        for (int mt = 0; mt < 2; mt++) {
            const int r0 = base + mt * 16 + grp;
            #pragma unroll
            for (int nt = 0; nt < 8; nt++) {
                const int col = nt * 8 + 2 * tig;
                *reinterpret_cast<float2*>(dst +  r0      * DIM + col) =
                    make_float2(acc[mt][nt][0], acc[mt][nt][1]);
                *reinterpret_cast<float2*>(dst + (r0 + 8) * DIM + col) =
                    make_float2(acc[mt][nt][2], acc[mt][nt][3]);
            }
        }
    }
}

// ---------------------------------------------------------------------------
extern "C" void kernel_launch(void* const* d_in, const int* in_sizes, int n_in,
                              void* d_out, int out_size)
{
    const float* wkv = (const float*)d_in[0];
    const float* pL  = (const float*)d_in[1];
    const float* pR  = (const float*)d_in[2];
    float* out       = (float*)d_out;

    // Unconditional; immediate host-side API, idempotent, capture-safe.
    cudaFuncSetAttribute(bilat_kernel,
                         cudaFuncAttributeMaxDynamicSharedMemorySize,
                         SMEM_TOTAL_BYTES);

    cayley_kernel<<<2 * NUM_HEADS, 256>>>(pL, pR);
    bilat_kernel<<<NUM_HEADS * 64, 128, SMEM_TOTAL_BYTES>>>(wkv, out);
}

// round 8
// speedup vs baseline: 1.9893x; 1.1417x over previous
#include <cuda_runtime.h>
#include <cuda_bf16.h>
#include <cstdint>

// ---------------------------------------------------------------------------
// BilateralRotation: out[b,c] = R1[c] @ wkv[b,c] @ R2[c]
//   R = Cayley(p) = (I - A)(I + A)^{-1} = (I + A)^{-1}(I - A)
//
// Stage 1: cayley_kernel — register-resident GJ on [I+A | I-A] -> R directly.
//          Chunked unroll (4 x 16): static register indices, ~16KB code (I$-fit).
// Stage 2: bilat_kernel — R5 structure (XOR-swizzled pitch-64 SMEM, scalar
//          frag LDS, cp.async) at 256 threads = 4 warp-pairs sharing one R
//          staging. SMEM 96KB -> 2 CTAs/SM = 16 warps/SM.
// ---------------------------------------------------------------------------

#define NUM_HEADS 32
#define DIM 64
#define MATF 4096                        // floats per 64x64 buffer (16 KB)
#define SMEM_TOTAL_BYTES (6 * MATF * 4)  // sR1, sR2T, sW0..3 = 98304 B

__device__ float g_R1 [NUM_HEADS * DIM * DIM];   // R1 row-major [i][l]
__device__ float g_R2T[NUM_HEADS * DIM * DIM];   // R2 transposed [n][k]

__device__ __forceinline__ float tf32r(float x) {
    uint32_t u;
    asm("cvt.rna.tf32.f32 %0, %1;" : "=r"(u) : "f"(x));
    return __uint_as_float(u);
}

__device__ __forceinline__ void cp16(float* dst_smem, const void* src) {
    uint32_t d = (uint32_t)__cvta_generic_to_shared(dst_smem);
    asm volatile("cp.async.ca.shared.global [%0], [%1], 16;\n" :: "r"(d), "l"(src));
}
#define CP_COMMIT() asm volatile("cp.async.commit_group;\n")
#define CP_WAIT0()  asm volatile("cp.async.wait_group 0;\n" ::: "memory")
#define CP_WAIT1()  asm volatile("cp.async.wait_group 1;\n" ::: "memory")

__device__ __forceinline__ void pbar(int id) {
    asm volatile("bar.sync %0, 64;" :: "r"(id) : "memory");
}

// ---------------------------------------------------------------------------
// Stage 1: Cayley. One block per (side, head), 256 threads.
// Thread (r = tid>>2, q = tid&3) owns 16 cols of row r of [M | X],
// M = I + A, X = I - A, register resident. k-loop split 4 chunks x 16
// unrolled: register indices stay static, code stays I$-resident.
// Unpivoted GJ safe: symmetric part of I+A is I (SPD). End: X = R.
// ---------------------------------------------------------------------------
__global__ __launch_bounds__(256) void cayley_kernel(
    const float* __restrict__ pL, const float* __restrict__ pR)
{
    const int side = blockIdx.x >> 5;
    const int h    = blockIdx.x & 31;
    const float* p = (side ? pR : pL) + h * DIM * DIM;

    const int tid = threadIdx.x;
    const int r   = tid >> 2;
    const int q   = tid & 3;
    const int cb  = q * 16;

    __shared__ float rowM[DIM], rowX[DIM], colM[DIM];

    float m[16], x[16];
    #pragma unroll
    for (int j = 0; j < 16; j++) {
        int c = cb + j;
        float a = 0.5f * (p[r * DIM + c] - p[c * DIM + r]);
        float id = (r == c) ? 1.0f : 0.0f;
        m[j] = id + a;
        x[j] = id - a;
    }
    __syncthreads();

    #pragma unroll 1
    for (int chunk = 0; chunk < 4; chunk++) {
        #pragma unroll
        for (int kk = 0; kk < 16; kk++) {
            const int k = (chunk << 4) + kk;
            if (r == k) {
                #pragma unroll
                for (int j = 0; j < 16; j++) { rowM[cb + j] = m[j]; rowX[cb + j] = x[j]; }
            }
            if (chunk == q) colM[r] = m[kk];     // kk literal -> static index
            __syncthreads();

            const float invp = 1.0f / rowM[k];
            if (r == k) {
                #pragma unroll
                for (int j = 0; j < 16; j++) { m[j] *= invp; x[j] *= invp; }
            } else {
                const float f = colM[r] * invp;
                #pragma unroll
                for (int j = 0; j < 16; j++) {
                    m[j] -= f * rowM[cb + j];
                    x[j] -= f * rowX[cb + j];
                }
            }
            __syncthreads();
        }
    }

    // x[] now holds R[r][cb..cb+15]
    if (side == 0) {
        float* dst = g_R1 + h * DIM * DIM;
        #pragma unroll
        for (int j = 0; j < 16; j++) dst[r * DIM + cb + j] = x[j];
    } else {
        float* dst = g_R2T + h * DIM * DIM;
        #pragma unroll
        for (int j = 0; j < 16; j++) dst[(cb + j) * DIM + r] = x[j];
    }
}

// ---------------------------------------------------------------------------
// Stage 2 GEMM core (R5-proven): 32x64 warp tile, XOR-swizzled pitch-64 SMEM
//   elem (row, col) at [row*64 + (col ^ (4*(row&7)))]; conflict-free for all
//   fragment loads and the T^T scatter stores.
// ---------------------------------------------------------------------------
template<bool CVTA>
__device__ __forceinline__ void gemm32x64(
    const float* __restrict__ Am,   // A [m][k] swizzled; rows base..base+31
    const float* __restrict__ Bm,   // B [n][k] swizzled
    float acc[2][8][4], int base, int grp, int tig)
{
    #pragma unroll
    for (int kb = 0; kb < DIM; kb += 8) {
        const int cx0 = (kb + tig)     ^ (grp << 2);
        const int cx4 = (kb + tig + 4) ^ (grp << 2);
        uint32_t a[2][4];
        #pragma unroll
        for (int mt = 0; mt < 2; mt++) {
            const int r0 = base + mt * 16 + grp;
            float a0 = Am[ r0      * DIM + cx0];
            float a1 = Am[(r0 + 8) * DIM + cx0];
            float a2 = Am[ r0      * DIM + cx4];
            float a3 = Am[(r0 + 8) * DIM + cx4];
            if (CVTA) { a0 = tf32r(a0); a1 = tf32r(a1); a2 = tf32r(a2); a3 = tf32r(a3); }
            a[mt][0] = __float_as_uint(a0); a[mt][1] = __float_as_uint(a1);
            a[mt][2] = __float_as_uint(a2); a[mt][3] = __float_as_uint(a3);
        }
        #pragma unroll
        for (int nt = 0; nt < 8; nt++) {
            const int n = nt * 8 + grp;
            uint32_t b0 = __float_as_uint(Bm[n * DIM + cx0]);
            uint32_t b1 = __float_as_uint(Bm[n * DIM + cx4]);
            #pragma unroll
            for (int mt = 0; mt < 2; mt++) {
                asm volatile(
                    "mma.sync.aligned.m16n8k8.row.col.f32.tf32.tf32.f32 "
                    "{%0,%1,%2,%3}, {%4,%5,%6,%7}, {%8,%9}, {%0,%1,%2,%3};\n"
                    : "+f"(acc[mt][nt][0]), "+f"(acc[mt][nt][1]),
                      "+f"(acc[mt][nt][2]), "+f"(acc[mt][nt][3])
                    : "r"(a[mt][0]), "r"(a[mt][1]), "r"(a[mt][2]), "r"(a[mt][3]),
                      "r"(b0), "r"(b1));
            }
        }
    }
}

// ---------------------------------------------------------------------------
// Stage 2: 2048 blocks (head-major), 256 threads = 4 warp-pairs, 2 passes
// -> 8 batches/block sharing one R staging. One W/T buffer per pair.
// ---------------------------------------------------------------------------
__global__ __launch_bounds__(256, 2) void bilat_kernel(
    const float* __restrict__ wkv, float* __restrict__ out)
{
    extern __shared__ float smem[];
    float* sR1  = smem;                  // A of GEMM2 (pre-rounded)
    float* sR2T = smem + MATF;           // B of GEMM1 (pre-rounded)

    const int blk  = blockIdx.x;
    const int head = blk >> 6;           // head-major: R matrices L2-hot
    const int g    = blk & 63;

    const int tid    = threadIdx.x;
    const int lane   = tid & 31;
    const int warp   = tid >> 5;
    const int pairid = warp >> 1;        // 0..3
    const int w2     = warp & 1;
    const int grp    = lane >> 2;        // 0..7
    const int tig    = lane & 3;         // 0..3
    const int base   = w2 * 32;
    const int tp     = tid & 63;

    float* sW = smem + 2 * MATF + pairid * MATF;

    // ---- cp.async: R1 + R2T (raw), group 0 ----
    {
        const float4* r1g = reinterpret_cast<const float4*>(g_R1)  + (size_t)head * 1024;
        const float4* r2g = reinterpret_cast<const float4*>(g_R2T) + (size_t)head * 1024;
        #pragma unroll 4
        for (int ci = tid; ci < 1024; ci += 256) {
            int r = ci >> 4, c = (ci & 15) << 2;
            int cx = c ^ ((r & 7) << 2);
            cp16(&sR1 [r * DIM + cx], r1g + ci);
            cp16(&sR2T[r * DIM + cx], r2g + ci);
        }
    }
    CP_COMMIT();

    // ---- cp.async: W for pass 0 (raw), group 1 ----
    {
        const int b0 = g * 8 + pairid;
        const float4* wsrc = reinterpret_cast<const float4*>(wkv)
                           + (size_t)(b0 * NUM_HEADS + head) * 1024;
        #pragma unroll 4
        for (int ci = tp; ci < 1024; ci += 64) {
            int r = ci >> 4, c = (ci & 15) << 2;
            int cx = c ^ ((r & 7) << 2);
            cp16(&sW[r * DIM + cx], wsrc + ci);
        }
    }
    CP_COMMIT();

    // ---- R arrived: in-place tf32 rounding of sR1+sR2T ----
    CP_WAIT1();
    __syncthreads();
    {
        float4* rp = reinterpret_cast<float4*>(smem);   // first 8192 floats
        #pragma unroll 4
        for (int i = tid; i < 2048; i += 256) {
            float4 v = rp[i];
            v.x = tf32r(v.x); v.y = tf32r(v.y); v.z = tf32r(v.z); v.w = tf32r(v.w);
            rp[i] = v;
        }
    }
    __syncthreads();

    #pragma unroll 1
    for (int pass = 0; pass < 2; pass++) {
        const int b = g * 8 + pass * 4 + pairid;

        CP_WAIT0();            // this pass's W chunks (own thread) done
        pbar(1 + pairid);      // all pair threads' chunks visible

        // ---- GEMM1: T = W @ R2  (A = raw W, inline cvt; B = sR2T) ----
        float acc[2][8][4];
        #pragma unroll
        for (int mt = 0; mt < 2; mt++)
            #pragma unroll
            for (int nt = 0; nt < 8; nt++)
                { acc[mt][nt][0]=0.f; acc[mt][nt][1]=0.f; acc[mt][nt][2]=0.f; acc[mt][nt][3]=0.f; }
        gemm32x64<true>(sW, sR2T, acc, base, grp, tig);
        pbar(1 + pairid);      // pair done reading W

        // ---- write T^T into sW (swizzled, tf32-rounded) ----
        #pragma unroll
        for (int mt = 0; mt < 2; mt++) {
            const int r0 = base + mt * 16 + grp;
            #pragma unroll
            for (int nt = 0; nt < 8; nt++) {
                const int c0 = nt * 8 + 2 * tig;
                const int c1 = c0 + 1;
                sW[c0 * DIM + ( r0      ^ ((c0 & 7) << 2))] = tf32r(acc[mt][nt][0]);
                sW[c1 * DIM + ( r0      ^ ((c1 & 7) << 2))] = tf32r(acc[mt][nt][1]);
                sW[c0 * DIM + ((r0 + 8) ^ ((c0 & 7) << 2))] = tf32r(acc[mt][nt][2]);
                sW[c1 * DIM + ((r0 + 8) ^ ((c1 & 7) << 2))] = tf32r(acc[mt][nt][3]);
            }
        }
        pbar(1 + pairid);      // T^T visible to the pair

        // ---- GEMM2: out = R1 @ T  (A = sR1, B = T^T in sW) ----
        #pragma unroll
        for (int mt = 0; mt < 2; mt++)
            #pragma unroll
            for (int nt = 0; nt < 8; nt++)
                { acc[mt][nt][0]=0.f; acc[mt][nt][1]=0.f; acc[mt][nt][2]=0.f; acc[mt][nt][3]=0.f; }
        gemm32x64<false>(sR1, sW, acc, base, grp, tig);
        pbar(1 + pairid);      // sW free

        // ---- prefetch next pass's W (overlaps epilogue stores) ----
        if (pass == 0) {
            const int bn = b + 4;
            const float4* wsrc = reinterpret_cast<const float4*>(wkv)
                               + (size_t)(bn * NUM_HEADS + head) * 1024;
            #pragma unroll 4
            for (int ci = tp; ci < 1024; ci += 64) {
                int r = ci >> 4, c = (ci & 15) << 2;
                int cx = c ^ ((r & 7) << 2);
                cp16(&sW[r * DIM + cx], wsrc + ci);
            }
            CP_COMMIT();
        }

        // ---- epilogue: coalesced float2 stores ----
        float* dst = out + (size_t)(b * NUM_HEADS + head) * (DIM * DIM);
        #pragma unroll
        for (int mt = 0; mt < 2; mt++) {
            const int r0 = base + mt * 16 + grp;
            #pragma unroll
            for (int nt = 0; nt < 8; nt++) {
                const int col = nt * 8 + 2 * tig;
                *reinterpret_cast<float2*>(dst +  r0      * DIM + col) =
                    make_float2(acc[mt][nt][0], acc[mt][nt][1]);
                *reinterpret_cast<float2*>(dst + (r0 + 8) * DIM + col) =
                    make_float2(acc[mt][nt][2], acc[mt][nt][3]);
            }
        }
    }
}

// ---------------------------------------------------------------------------
extern "C" void kernel_launch(void* const* d_in, const int* in_sizes, int n_in,
                              void* d_out, int out_size)
{
    const float* wkv = (const float*)d_in[0];
    const float* pL  = (const float*)d_in[1];
    const float* pR  = (const float*)d_in[2];
    float* out       = (float*)d_out;

    // Unconditional; immediate host-side API, idempotent, capture-safe.
    cudaFuncSetAttribute(bilat_kernel,
                         cudaFuncAttributeMaxDynamicSharedMemorySize,
                         SMEM_TOTAL_BYTES);

    cayley_kernel<<<2 * NUM_HEADS, 256>>>(pL, pR);
    bilat_kernel<<<NUM_HEADS * 64, 256, SMEM_TOTAL_BYTES>>>(wkv, out);
}

// round 9
// speedup vs baseline: 2.2399x; 1.1260x over previous
#include <cuda_runtime.h>
#include <cuda_bf16.h>
#include <cstdint>

// ---------------------------------------------------------------------------
// BilateralRotation: out[b,c] = R1[c] @ wkv[b,c] @ R2[c]
//   R = Cayley(p) = (I - A)(I + A)^{-1} = (I + A)^{-1}(I - A)
//
// Stage 1: cayley_kernel — register-resident GJ on [I+A | I-A] -> R directly.
//          Chunked unroll (4 x 16): static reg indices, I$-resident code.
// Stage 2: bilat_kernel — R5 config: 4096 blocks (head-major), 128 thr,
//          3 CTAs/SM, XOR-swizzled pitch-64 SMEM, cp.async staging,
//          tf32 mma.sync. Launched with PDL: starts W loads while cayley
//          still runs, then cudaGridDependencySynchronize() before R loads.
// ---------------------------------------------------------------------------

#define NUM_HEADS 32
#define DIM 64
#define MATF 4096                       // floats per 64x64 buffer (16 KB)
#define SMEM_TOTAL_BYTES (4 * MATF * 4) // sR1, sR2T, sW0, sW1 = 65536 B

__device__ float g_R1 [NUM_HEADS * DIM * DIM];   // R1 row-major [i][l]
__device__ float g_R2T[NUM_HEADS * DIM * DIM];   // R2 transposed [n][k]

__device__ __forceinline__ float tf32r(float x) {
    uint32_t u;
    asm("cvt.rna.tf32.f32 %0, %1;" : "=r"(u) : "f"(x));
    return __uint_as_float(u);
}

__device__ __forceinline__ void cp16_ca(float* dst_smem, const void* src) {
    uint32_t d = (uint32_t)__cvta_generic_to_shared(dst_smem);
    asm volatile("cp.async.ca.shared.global [%0], [%1], 16;\n" :: "r"(d), "l"(src));
}
__device__ __forceinline__ void cp16_cg(float* dst_smem, const void* src) {
    uint32_t d = (uint32_t)__cvta_generic_to_shared(dst_smem);
    asm volatile("cp.async.cg.shared.global [%0], [%1], 16;\n" :: "r"(d), "l"(src));
}
#define CP_COMMIT() asm volatile("cp.async.commit_group;\n")
#define CP_WAIT0()  asm volatile("cp.async.wait_group 0;\n" ::: "memory")

__device__ __forceinline__ void pbar(int id) {
    asm volatile("bar.sync %0, 64;" :: "r"(id) : "memory");
}

// ---------------------------------------------------------------------------
// Stage 1: Cayley. One block per (side, head), 256 threads.
// Thread (r = tid>>2, q = tid&3) owns 16 cols of row r of [M | X],
// M = I + A, X = I - A, register resident. k-loop split 4 chunks x 16
// unrolled: register indices stay static, code stays I$-resident.
// Unpivoted GJ safe: symmetric part of I+A is I (SPD). End: X = R.
// ---------------------------------------------------------------------------
__global__ __launch_bounds__(256) void cayley_kernel(
    const float* __restrict__ pL, const float* __restrict__ pR)
{
    const int side = blockIdx.x >> 5;
    const int h    = blockIdx.x & 31;
    const float* p = (side ? pR : pL) + h * DIM * DIM;

    const int tid = threadIdx.x;
    const int r   = tid >> 2;
    const int q   = tid & 3;
    const int cb  = q * 16;

    __shared__ float rowM[DIM], rowX[DIM], colM[DIM];

    float m[16], x[16];
    #pragma unroll
    for (int j = 0; j < 16; j++) {
        int c = cb + j;
        float a = 0.5f * (p[r * DIM + c] - p[c * DIM + r]);
        float id = (r == c) ? 1.0f : 0.0f;
        m[j] = id + a;
        x[j] = id - a;
    }
    __syncthreads();

    #pragma unroll 1
    for (int chunk = 0; chunk < 4; chunk++) {
        #pragma unroll
        for (int kk = 0; kk < 16; kk++) {
            const int k = (chunk << 4) + kk;
            if (r == k) {
                #pragma unroll
                for (int j = 0; j < 16; j++) { rowM[cb + j] = m[j]; rowX[cb + j] = x[j]; }
            }
            if (chunk == q) colM[r] = m[kk];     // kk literal -> static index
            __syncthreads();

            const float invp = 1.0f / rowM[k];
            if (r == k) {
                #pragma unroll
                for (int j = 0; j < 16; j++) { m[j] *= invp; x[j] *= invp; }
            } else {
                const float f = colM[r] * invp;
                #pragma unroll
                for (int j = 0; j < 16; j++) {
                    m[j] -= f * rowM[cb + j];
                    x[j] -= f * rowX[cb + j];
                }
            }
            __syncthreads();
        }
    }

    // x[] now holds R[r][cb..cb+15]
    if (side == 0) {
        float* dst = g_R1 + h * DIM * DIM;
        #pragma unroll
        for (int j = 0; j < 16; j++) dst[r * DIM + cb + j] = x[j];
    } else {
        float* dst = g_R2T + h * DIM * DIM;
        #pragma unroll
        for (int j = 0; j < 16; j++) dst[(cb + j) * DIM + r] = x[j];
    }
}

// ---------------------------------------------------------------------------
// Stage 2 GEMM core (R5-proven): 32x64 warp tile, XOR-swizzled pitch-64 SMEM
//   elem (row, col) at [row*64 + (col ^ (4*(row&7)))]; conflict-free for all
//   fragment loads and the T^T scatter stores.
// ---------------------------------------------------------------------------
template<bool CVTA>
__device__ __forceinline__ void gemm32x64(
    const float* __restrict__ Am,   // A [m][k] swizzled; rows base..base+31
    const float* __restrict__ Bm,   // B [n][k] swizzled
    float acc[2][8][4], int base, int grp, int tig)
{
    #pragma unroll
    for (int kb = 0; kb < DIM; kb += 8) {
        const int cx0 = (kb + tig)     ^ (grp << 2);
        const int cx4 = (kb + tig + 4) ^ (grp << 2);
        uint32_t a[2][4];
        #pragma unroll
        for (int mt = 0; mt < 2; mt++) {
            const int r0 = base + mt * 16 + grp;
            float a0 = Am[ r0      * DIM + cx0];
            float a1 = Am[(r0 + 8) * DIM + cx0];
            float a2 = Am[ r0      * DIM + cx4];
            float a3 = Am[(r0 + 8) * DIM + cx4];
            if (CVTA) { a0 = tf32r(a0); a1 = tf32r(a1); a2 = tf32r(a2); a3 = tf32r(a3); }
            a[mt][0] = __float_as_uint(a0); a[mt][1] = __float_as_uint(a1);
            a[mt][2] = __float_as_uint(a2); a[mt][3] = __float_as_uint(a3);
        }
        #pragma unroll
        for (int nt = 0; nt < 8; nt++) {
            const int n = nt * 8 + grp;
            uint32_t b0 = __float_as_uint(Bm[n * DIM + cx0]);
            uint32_t b1 = __float_as_uint(Bm[n * DIM + cx4]);
            #pragma unroll
            for (int mt = 0; mt < 2; mt++) {
                asm volatile(
                    "mma.sync.aligned.m16n8k8.row.col.f32.tf32.tf32.f32 "
                    "{%0,%1,%2,%3}, {%4,%5,%6,%7}, {%8,%9}, {%0,%1,%2,%3};\n"
                    : "+f"(acc[mt][nt][0]), "+f"(acc[mt][nt][1]),
                      "+f"(acc[mt][nt][2]), "+f"(acc[mt][nt][3])
                    : "r"(a[mt][0]), "r"(a[mt][1]), "r"(a[mt][2]), "r"(a[mt][3]),
                      "r"(b0), "r"(b1));
            }
        }
    }
}

// ---------------------------------------------------------------------------
// Stage 2: 4096 blocks (head-major), 128 threads = 2 warp-pairs, 2 passes
// -> 4 batches/block sharing one R staging. PDL: W loads issued before the
// grid dependency resolves; R loads after.
// ---------------------------------------------------------------------------
__global__ __launch_bounds__(128, 3) void bilat_kernel(
    const float* __restrict__ wkv, float* __restrict__ out)
{
    extern __shared__ float smem[];
    float* sR1  = smem;                  // A of GEMM2 (pre-rounded)
    float* sR2T = smem + MATF;           // B of GEMM1 (pre-rounded)

    const int blk  = blockIdx.x;
    const int head = blk >> 7;           // head-major: R matrices L2-hot
    const int g    = blk & 127;

    const int tid    = threadIdx.x;
    const int lane   = tid & 31;
    const int warp   = tid >> 5;
    const int pairid = warp >> 1;        // 0,1
    const int w2     = warp & 1;
    const int grp    = lane >> 2;        // 0..7
    const int tig    = lane & 3;         // 0..3
    const int base   = w2 * 32;
    const int tp     = tid & 63;

    float* sW = smem + 2 * MATF + pairid * MATF;

    // ---- cp.async (cg): W for pass 0 — independent of cayley output ----
    {
        const int b0 = g * 4 + pairid;
        const float4* wsrc = reinterpret_cast<const float4*>(wkv)
                           + (size_t)(b0 * NUM_HEADS + head) * 1024;
        #pragma unroll 4
        for (int ci = tp; ci < 1024; ci += 64) {
            int r = ci >> 4, c = (ci & 15) << 2;
            int cx = c ^ ((r & 7) << 2);
            cp16_cg(&sW[r * DIM + cx], wsrc + ci);
        }
    }
    CP_COMMIT();

    // ---- wait for cayley's R writes to be visible (PDL dependency) ----
    cudaGridDependencySynchronize();

    // ---- cp.async (ca): R1 + R2T ----
    {
        const float4* r1g = reinterpret_cast<const float4*>(g_R1)  + (size_t)head * 1024;
        const float4* r2g = reinterpret_cast<const float4*>(g_R2T) + (size_t)head * 1024;
        #pragma unroll 4
        for (int ci = tid; ci < 1024; ci += 128) {
            int r = ci >> 4, c = (ci & 15) << 2;
            int cx = c ^ ((r & 7) << 2);
            cp16_ca(&sR1 [r * DIM + cx], r1g + ci);
            cp16_ca(&sR2T[r * DIM + cx], r2g + ci);
        }
    }
    CP_COMMIT();

    // ---- all staging done: in-place tf32 rounding of sR1+sR2T ----
    CP_WAIT0();
    __syncthreads();
    {
        float4* rp = reinterpret_cast<float4*>(smem);   // first 8192 floats
        #pragma unroll 4
        for (int i = tid; i < 2048; i += 128) {
            float4 v = rp[i];
            v.x = tf32r(v.x); v.y = tf32r(v.y); v.z = tf32r(v.z); v.w = tf32r(v.w);
            rp[i] = v;
        }
    }
    __syncthreads();

    #pragma unroll 1
    for (int pass = 0; pass < 2; pass++) {
        const int b = g * 4 + pass * 2 + pairid;

        CP_WAIT0();            // this pass's W chunks (own thread) done
        pbar(1 + pairid);      // all pair threads' chunks visible

        // ---- GEMM1: T = W @ R2  (A = raw W, inline cvt; B = sR2T) ----
        float acc[2][8][4];
        #pragma unroll
        for (int mt = 0; mt < 2; mt++)
            #pragma unroll
            for (int nt = 0; nt < 8; nt++)
                { acc[mt][nt][0]=0.f; acc[mt][nt][1]=0.f; acc[mt][nt][2]=0.f; acc[mt][nt][3]=0.f; }
        gemm32x64<true>(sW, sR2T, acc, base, grp, tig);
        pbar(1 + pairid);      // pair done reading W

        // ---- write T^T into sW (swizzled, tf32-rounded) ----
        #pragma unroll
        for (int mt = 0; mt < 2; mt++) {
            const int r0 = base + mt * 16 + grp;
            #pragma unroll
            for (int nt = 0; nt < 8; nt++) {
                const int c0 = nt * 8 + 2 * tig;
                const int c1 = c0 + 1;
                sW[c0 * DIM + ( r0      ^ ((c0 & 7) << 2))] = tf32r(acc[mt][nt][0]);
                sW[c1 * DIM + ( r0      ^ ((c1 & 7) << 2))] = tf32r(acc[mt][nt][1]);
                sW[c0 * DIM + ((r0 + 8) ^ ((c0 & 7) << 2))] = tf32r(acc[mt][nt][2]);
                sW[c1 * DIM + ((r0 + 8) ^ ((c1 & 7) << 2))] = tf32r(acc[mt][nt][3]);
            }
        }
        pbar(1 + pairid);      // T^T visible to the pair

        // ---- GEMM2: out = R1 @ T  (A = sR1, B = T^T in sW) ----
        #pragma unroll
        for (int mt = 0; mt < 2; mt++)
            #pragma unroll
            for (int nt = 0; nt < 8; nt++)
                { acc[mt][nt][0]=0.f; acc[mt][nt][1]=0.f; acc[mt][nt][2]=0.f; acc[mt][nt][3]=0.f; }
        gemm32x64<false>(sR1, sW, acc, base, grp, tig);
        pbar(1 + pairid);      // sW free

        // ---- prefetch next pass's W (overlaps epilogue stores) ----
        if (pass == 0) {
            const int bn = b + 2;
            const float4* wsrc = reinterpret_cast<const float4*>(wkv)
                               + (size_t)(bn * NUM_HEADS + head) * 1024;
            #pragma unroll 4
            for (int ci = tp; ci < 1024; ci += 64) {
                int r = ci >> 4, c = (ci & 15) << 2;
                int cx = c ^ ((r & 7) << 2);
                cp16_cg(&sW[r * DIM + cx], wsrc + ci);
            }
            CP_COMMIT();
        }

        // ---- epilogue: coalesced float2 stores ----
        float* dst = out + (size_t)(b * NUM_HEADS + head) * (DIM * DIM);
        #pragma unroll
        for (int mt = 0; mt < 2; mt++) {
            const int r0 = base + mt * 16 + grp;
            #pragma unroll
            for (int nt = 0; nt < 8; nt++) {
                const int col = nt * 8 + 2 * tig;
                *reinterpret_cast<float2*>(dst +  r0      * DIM + col) =
                    make_float2(acc[mt][nt][0], acc[mt][nt][1]);
                *reinterpret_cast<float2*>(dst + (r0 + 8) * DIM + col) =
                    make_float2(acc[mt][nt][2], acc[mt][nt][3]);
            }
        }
    }
}

// ---------------------------------------------------------------------------
extern "C" void kernel_launch(void* const* d_in, const int* in_sizes, int n_in,
                              void* d_out, int out_size)
{
    const float* wkv = (const float*)d_in[0];
    const float* pL  = (const float*)d_in[1];
    const float* pR  = (const float*)d_in[2];
    float* out       = (float*)d_out;

    // Unconditional; immediate host-side API, idempotent, capture-safe.
    cudaFuncSetAttribute(bilat_kernel,
                         cudaFuncAttributeMaxDynamicSharedMemorySize,
                         SMEM_TOTAL_BYTES);

    cayley_kernel<<<2 * NUM_HEADS, 256>>>(pL, pR);

    // PDL launch: bilat starts while cayley runs; dependency resolved by
    // cudaGridDependencySynchronize() inside bilat before it reads g_R*.
    cudaLaunchConfig_t cfg = {};
    cfg.gridDim         = dim3(NUM_HEADS * 128, 1, 1);
    cfg.blockDim        = dim3(128, 1, 1);
    cfg.dynamicSmemBytes = SMEM_TOTAL_BYTES;
    cfg.stream          = 0;
    cudaLaunchAttribute attr[1];
    attr[0].id = cudaLaunchAttributeProgrammaticStreamSerialization;
    attr[0].val.programmaticStreamSerializationAllowed = 1;
    cfg.attrs    = attr;
    cfg.numAttrs = 1;
    cudaLaunchKernelEx(&cfg, bilat_kernel, wkv, out);
}

// round 10
// speedup vs baseline: 2.2619x; 1.0098x over previous
#include <cuda_runtime.h>
#include <cuda_bf16.h>
#include <cstdint>

// ---------------------------------------------------------------------------
// BilateralRotation: out[b,c] = R1[c] @ wkv[b,c] @ R2[c]
//   R = Cayley(p) = (I - A)(I + A)^{-1} = (I + A)^{-1}(I - A)
//
// Stage 1: cayley_kernel — register-resident GJ on [I+A | I-A] -> R directly.
// Stage 2: bilat_kernel — register-chained double GEMM:
//          GEMM1: Tt = R2T @ W^T  (A = R2T smem, B = W natural layout smem)
//          GEMM2: out = R1 @ T    (A = R1 smem, B = Tt FROM REGISTERS)
//          T never touches SMEM. All frag loads are conflict-free float2
//          (pitch 72, k-relabel slot tig -> k = 2*tig). PDL overlap.
// ---------------------------------------------------------------------------

#define NUM_HEADS 32
#define DIM 64
#define PITCH 72                         // pair-bank = 4*grp+tig per half-warp
#define MATP (DIM * PITCH)               // 4608 floats = 18432 B
#define SMEM_TOTAL_BYTES (4 * MATP * 4)  // sR1, sR2T, sW0, sW1 = 73728 B

__device__ float g_R1 [NUM_HEADS * DIM * DIM];   // R1 row-major [i][r]
__device__ float g_R2T[NUM_HEADS * DIM * DIM];   // R2 transposed [j][l]

__device__ __forceinline__ float tf32r(float x) {
    uint32_t u;
    asm("cvt.rna.tf32.f32 %0, %1;" : "=r"(u) : "f"(x));
    return __uint_as_float(u);
}

__device__ __forceinline__ void cp16_ca(float* dst_smem, const void* src) {
    uint32_t d = (uint32_t)__cvta_generic_to_shared(dst_smem);
    asm volatile("cp.async.ca.shared.global [%0], [%1], 16;\n" :: "r"(d), "l"(src));
}
__device__ __forceinline__ void cp16_cg(float* dst_smem, const void* src) {
    uint32_t d = (uint32_t)__cvta_generic_to_shared(dst_smem);
    asm volatile("cp.async.cg.shared.global [%0], [%1], 16;\n" :: "r"(d), "l"(src));
}
#define CP_COMMIT() asm volatile("cp.async.commit_group;\n")
#define CP_WAIT0()  asm volatile("cp.async.wait_group 0;\n" ::: "memory")

__device__ __forceinline__ void pbar(int id) {
    asm volatile("bar.sync %0, 64;" :: "r"(id) : "memory");
}

#define MMA_TF32(D0,D1,D2,D3, A0,A1,A2,A3, B0,B1)                            \
    asm volatile(                                                            \
        "mma.sync.aligned.m16n8k8.row.col.f32.tf32.tf32.f32 "                \
        "{%0,%1,%2,%3}, {%4,%5,%6,%7}, {%8,%9}, {%0,%1,%2,%3};\n"            \
        : "+f"(D0), "+f"(D1), "+f"(D2), "+f"(D3)                             \
        : "r"(A0), "r"(A1), "r"(A2), "r"(A3), "r"(B0), "r"(B1))

// ---------------------------------------------------------------------------
// Stage 1: Cayley. One block per (side, head), 256 threads.
// Chunked unroll (4 x 16): static reg indices, I$-resident code.
// Unpivoted GJ safe: symmetric part of I+A is I (SPD). End: X = R.
// ---------------------------------------------------------------------------
__global__ __launch_bounds__(256) void cayley_kernel(
    const float* __restrict__ pL, const float* __restrict__ pR)
{
    const int side = blockIdx.x >> 5;
    const int h    = blockIdx.x & 31;
    const float* p = (side ? pR : pL) + h * DIM * DIM;

    const int tid = threadIdx.x;
    const int r   = tid >> 2;
    const int q   = tid & 3;
    const int cb  = q * 16;

    __shared__ float rowM[DIM], rowX[DIM], colM[DIM];

    float m[16], x[16];
    #pragma unroll
    for (int j = 0; j < 16; j++) {
        int c = cb + j;
        float a = 0.5f * (p[r * DIM + c] - p[c * DIM + r]);
        float id = (r == c) ? 1.0f : 0.0f;
        m[j] = id + a;
        x[j] = id - a;
    }
    __syncthreads();

    #pragma unroll 1
    for (int chunk = 0; chunk < 4; chunk++) {
        #pragma unroll
        for (int kk = 0; kk < 16; kk++) {
            const int k = (chunk << 4) + kk;
            if (r == k) {
                #pragma unroll
                for (int j = 0; j < 16; j++) { rowM[cb + j] = m[j]; rowX[cb + j] = x[j]; }
            }
            if (chunk == q) colM[r] = m[kk];     // kk literal -> static index
            __syncthreads();

            const float invp = 1.0f / rowM[k];
            if (r == k) {
                #pragma unroll
                for (int j = 0; j < 16; j++) { m[j] *= invp; x[j] *= invp; }
            } else {
                const float f = colM[r] * invp;
                #pragma unroll
                for (int j = 0; j < 16; j++) {
                    m[j] -= f * rowM[cb + j];
                    x[j] -= f * rowX[cb + j];
                }
            }
            __syncthreads();
        }
    }

    if (side == 0) {
        float* dst = g_R1 + h * DIM * DIM;
        #pragma unroll
        for (int j = 0; j < 16; j++) dst[r * DIM + cb + j] = x[j];
    } else {
        float* dst = g_R2T + h * DIM * DIM;
        #pragma unroll
        for (int j = 0; j < 16; j++) dst[(cb + j) * DIM + r] = x[j];
    }

    // Release the PDL edge as early as possible.
    cudaTriggerProgrammaticLaunchCompletion();
}

// ---------------------------------------------------------------------------
// Stage 2: 4096 blocks (head-major), 128 threads = 2 warp-pairs, 2 passes
// -> 4 batches/block sharing one R staging.
// Warp w2 owns j-columns [w2*32, w2*32+32) of its batch.
// ---------------------------------------------------------------------------
__global__ __launch_bounds__(128, 3) void bilat_kernel(
    const float* __restrict__ wkv, float* __restrict__ out)
{
    extern __shared__ float smem[];
    float* sR1  = smem;                  // A of GEMM2 (pre-rounded) [i][r]
    float* sR2T = smem + MATP;           // A of GEMM1 (pre-rounded) [j][l]

    const int blk  = blockIdx.x;
    const int head = blk >> 7;           // head-major: R matrices L2-hot
    const int g    = blk & 127;

    const int tid    = threadIdx.x;
    const int lane   = tid & 31;
    const int warp   = tid >> 5;
    const int pairid = warp >> 1;        // 0,1
    const int w2     = warp & 1;
    const int grp    = lane >> 2;        // 0..7
    const int tig    = lane & 3;         // 0..3
    const int base   = w2 * 32;          // this warp's j-range
    const int tp     = tid & 63;

    float* sW = smem + 2 * MATP + pairid * MATP;   // W natural [r][l]

    // ---- cp.async (cg): W for pass 0 — independent of cayley output ----
    {
        const int b0 = g * 4 + pairid;
        const float4* wsrc = reinterpret_cast<const float4*>(wkv)
                           + (size_t)(b0 * NUM_HEADS + head) * 1024;
        #pragma unroll 4
        for (int ci = tp; ci < 1024; ci += 64) {
            int r = ci >> 4, c4 = (ci & 15) << 2;
            cp16_cg(&sW[r * PITCH + c4], wsrc + ci);
        }
    }
    CP_COMMIT();

    // ---- wait for cayley's R writes (PDL dependency) ----
    cudaGridDependencySynchronize();

    // ---- cp.async (ca): R1 + R2T ----
    {
        const float4* r1g = reinterpret_cast<const float4*>(g_R1)  + (size_t)head * 1024;
        const float4* r2g = reinterpret_cast<const float4*>(g_R2T) + (size_t)head * 1024;
        #pragma unroll 4
        for (int ci = tid; ci < 1024; ci += 128) {
            int r = ci >> 4, c4 = (ci & 15) << 2;
            cp16_ca(&sR1 [r * PITCH + c4], r1g + ci);
            cp16_ca(&sR2T[r * PITCH + c4], r2g + ci);
        }
    }
    CP_COMMIT();

    // ---- staging done: in-place tf32 rounding of sR1+sR2T ----
    CP_WAIT0();
    __syncthreads();
    {
        float4* rp = reinterpret_cast<float4*>(smem);   // 2*MATP floats
        #pragma unroll 4
        for (int i = tid; i < (2 * MATP) / 4; i += 128) {
            float4 v = rp[i];
            v.x = tf32r(v.x); v.y = tf32r(v.y); v.z = tf32r(v.z); v.w = tf32r(v.w);
            rp[i] = v;
        }
    }
    __syncthreads();

    #pragma unroll 1
    for (int pass = 0; pass < 2; pass++) {
        const int b = g * 4 + pass * 2 + pairid;

        CP_WAIT0();            // this pass's W chunks (own thread) done
        pbar(1 + pairid);      // all pair threads' chunks visible

        // ---- GEMM1: Tt = R2T @ W^T ----
        // acc1[mt][nt]: rows j = base+mt*16+grp(+8), cols r = nt*8+2tig(+1)
        float acc1[2][8][4];
        #pragma unroll
        for (int mt = 0; mt < 2; mt++)
            #pragma unroll
            for (int nt = 0; nt < 8; nt++)
                { acc1[mt][nt][0]=0.f; acc1[mt][nt][1]=0.f; acc1[mt][nt][2]=0.f; acc1[mt][nt][3]=0.f; }

        #pragma unroll
        for (int kb = 0; kb < DIM; kb += 8) {
            const int kc = kb + 2 * tig;       // k-relabel: slot tig -> l = kb+2tig
            uint32_t a[2][4];
            #pragma unroll
            for (int mt = 0; mt < 2; mt++) {
                const int j0 = base + mt * 16 + grp;
                float2 va = *reinterpret_cast<const float2*>(&sR2T[ j0      * PITCH + kc]);
                float2 vb = *reinterpret_cast<const float2*>(&sR2T[(j0 + 8) * PITCH + kc]);
                a[mt][0] = __float_as_uint(va.x);  // slot tig
                a[mt][1] = __float_as_uint(vb.x);
                a[mt][2] = __float_as_uint(va.y);  // slot tig+4
                a[mt][3] = __float_as_uint(vb.y);
            }
            #pragma unroll
            for (int nt = 0; nt < 8; nt++) {
                const int r = nt * 8 + grp;
                float2 w = *reinterpret_cast<const float2*>(&sW[r * PITCH + kc]);
                uint32_t b0 = __float_as_uint(tf32r(w.x));
                uint32_t b1 = __float_as_uint(tf32r(w.y));
                #pragma unroll
                for (int mt = 0; mt < 2; mt++)
                    MMA_TF32(acc1[mt][nt][0], acc1[mt][nt][1], acc1[mt][nt][2], acc1[mt][nt][3],
                             a[mt][0], a[mt][1], a[mt][2], a[mt][3], b0, b1);
            }
        }
        pbar(1 + pairid);      // pair done reading W -> sW free

        // ---- prefetch next pass's W: overlaps ALL of GEMM2 + epilogue ----
        if (pass == 0) {
            const int bn = b + 2;
            const float4* wsrc = reinterpret_cast<const float4*>(wkv)
                               + (size_t)(bn * NUM_HEADS + head) * 1024;
            #pragma unroll 4
            for (int ci = tp; ci < 1024; ci += 64) {
                int r = ci >> 4, c4 = (ci & 15) << 2;
                cp16_cg(&sW[r * PITCH + c4], wsrc + ci);
            }
            CP_COMMIT();
        }

        // ---- round Tt to tf32 in registers ----
        #pragma unroll
        for (int mt = 0; mt < 2; mt++)
            #pragma unroll
            for (int nt = 0; nt < 8; nt++)
                #pragma unroll
                for (int c = 0; c < 4; c++)
                    acc1[mt][nt][c] = tf32r(acc1[mt][nt][c]);

        // ---- GEMM2: out = R1 @ T  (B = Tt from registers) ----
        // acc2[mt][nt]: rows i = mt*16+grp(+8), cols j = base+nt*8+2tig(+1)
        float acc2[4][4][4];
        #pragma unroll
        for (int mt = 0; mt < 4; mt++)
            #pragma unroll
            for (int nt = 0; nt < 4; nt++)
                { acc2[mt][nt][0]=0.f; acc2[mt][nt][1]=0.f; acc2[mt][nt][2]=0.f; acc2[mt][nt][3]=0.f; }

        #pragma unroll
        for (int rblk = 0; rblk < 8; rblk++) {
            const int kc = rblk * 8 + 2 * tig;   // k-relabel: slot tig -> r = rblk*8+2tig
            uint32_t a[4][4];
            #pragma unroll
            for (int mt = 0; mt < 4; mt++) {
                const int i0 = mt * 16 + grp;
                float2 va = *reinterpret_cast<const float2*>(&sR1[ i0      * PITCH + kc]);
                float2 vb = *reinterpret_cast<const float2*>(&sR1[(i0 + 8) * PITCH + kc]);
                a[mt][0] = __float_as_uint(va.x);
                a[mt][1] = __float_as_uint(vb.x);
                a[mt][2] = __float_as_uint(va.y);
                a[mt][3] = __float_as_uint(vb.y);
            }
            #pragma unroll
            for (int nt = 0; nt < 4; nt++) {
                // B frag: Tt[j = base+nt*8+grp][r = rblk*8+2tig(+1)] from acc1
                const uint32_t b0 = __float_as_uint(acc1[nt >> 1][rblk][(nt & 1) * 2    ]);
                const uint32_t b1 = __float_as_uint(acc1[nt >> 1][rblk][(nt & 1) * 2 + 1]);
                #pragma unroll
                for (int mt = 0; mt < 4; mt++)
                    MMA_TF32(acc2[mt][nt][0], acc2[mt][nt][1], acc2[mt][nt][2], acc2[mt][nt][3],
                             a[mt][0], a[mt][1], a[mt][2], a[mt][3], b0, b1);
            }
        }

        // ---- epilogue: coalesced float2 stores ----
        float* dst = out + (size_t)(b * NUM_HEADS + head) * (DIM * DIM);
        #pragma unroll
        for (int mt = 0; mt < 4; mt++) {
            const int i0 = mt * 16 + grp;
            #pragma unroll
            for (int nt = 0; nt < 4; nt++) {
                const int col = base + nt * 8 + 2 * tig;
                *reinterpret_cast<float2*>(dst +  i0      * DIM + col) =
                    make_float2(acc2[mt][nt][0], acc2[mt][nt][1]);
                *reinterpret_cast<float2*>(dst + (i0 + 8) * DIM + col) =
                    make_float2(acc2[mt][nt][2], acc2[mt][nt][3]);
            }
        }
    }
}

// ---------------------------------------------------------------------------
extern "C" void kernel_launch(void* const* d_in, const int* in_sizes, int n_in,
                              void* d_out, int out_size)
{
    const float* wkv = (const float*)d_in[0];
    const float* pL  = (const float*)d_in[1];
    const float* pR  = (const float*)d_in[2];
    float* out       = (float*)d_out;

    // Unconditional; immediate host-side API, idempotent, capture-safe.
    cudaFuncSetAttribute(bilat_kernel,
                         cudaFuncAttributeMaxDynamicSharedMemorySize,
                         SMEM_TOTAL_BYTES);

    cayley_kernel<<<2 * NUM_HEADS, 256>>>(pL, pR);

    // PDL launch: bilat starts while cayley runs; dependency resolved by
    // cudaGridDependencySynchronize() inside bilat before it reads g_R*.
    cudaLaunchConfig_t cfg = {};
    cfg.gridDim          = dim3(NUM_HEADS * 128, 1, 1);
    cfg.blockDim         = dim3(128, 1, 1);
    cfg.dynamicSmemBytes = SMEM_TOTAL_BYTES;
    cfg.stream           = 0;
    cudaLaunchAttribute attr[1];
    attr[0].id = cudaLaunchAttributeProgrammaticStreamSerialization;
    attr[0].val.programmaticStreamSerializationAllowed = 1;
    cfg.attrs    = attr;
    cfg.numAttrs = 1;
    cudaLaunchKernelEx(&cfg, bilat_kernel, wkv, out);
}

// round 11
// speedup vs baseline: 2.9995x; 1.3261x over previous
#include <cuda_runtime.h>
#include <cuda_fp16.h>
#include <cstdint>

// ---------------------------------------------------------------------------
// BilateralRotation: out[b,c] = R1[c] @ wkv[b,c] @ R2[c]
//   R = Cayley(p) = (I - A)(I + A)^{-1} = (I + A)^{-1}(I - A)
//
// Stage 1: cayley_kernel — register-resident GJ -> R directly, emitted fp16.
// Stage 2: bilat_kernel — register-chained double GEMM on fp16 m16n8k16:
//          GEMM1: Tt = R2T @ W^T  (A = fp16 R2T smem, B = f32 W smem, cvt)
//          GEMM2: out = R1 @ T    (A = fp16 R1 smem, B = Tt FROM REGISTERS)
//          fp16 mantissa == tf32 mantissa (10 bits) and |values| < ~10, so
//          accuracy matches the tf32 version. 55.3KB smem -> 4 CTAs/SM.
// ---------------------------------------------------------------------------

#define NUM_HEADS 32
#define DIM 64
#define PITCH  72                        // f32 W rows (floats)
#define PITCHH 72                        // fp16 R rows (halfs)
#define MATW (DIM * PITCH)               // 4608 f32  = 18432 B
#define MATH (DIM * PITCHH)              // 4608 half =  9216 B
#define SMEM_TOTAL_BYTES (2 * MATH * 2 + 2 * MATW * 4)   // 55296 B

__device__ __half g_R1h [NUM_HEADS * DIM * DIM];  // R1 row-major [i][r], fp16
__device__ __half g_R2Th[NUM_HEADS * DIM * DIM];  // R2^T [j][l], fp16

__device__ __forceinline__ uint32_t pack_h2(float lo, float hi) {
    __half2 h = __float22half2_rn(make_float2(lo, hi));
    return *reinterpret_cast<uint32_t*>(&h);
}

__device__ __forceinline__ void cp16_ca(void* dst_smem, const void* src) {
    uint32_t d = (uint32_t)__cvta_generic_to_shared(dst_smem);
    asm volatile("cp.async.ca.shared.global [%0], [%1], 16;\n" :: "r"(d), "l"(src));
}
__device__ __forceinline__ void cp16_cg(void* dst_smem, const void* src) {
    uint32_t d = (uint32_t)__cvta_generic_to_shared(dst_smem);
    asm volatile("cp.async.cg.shared.global [%0], [%1], 16;\n" :: "r"(d), "l"(src));
}
#define CP_COMMIT() asm volatile("cp.async.commit_group;\n")
#define CP_WAIT0()  asm volatile("cp.async.wait_group 0;\n" ::: "memory")

__device__ __forceinline__ void pbar(int id) {
    asm volatile("bar.sync %0, 64;" :: "r"(id) : "memory");
}

#define MMA_F16(D0,D1,D2,D3, A0,A1,A2,A3, B0,B1)                             \
    asm volatile(                                                            \
        "mma.sync.aligned.m16n8k16.row.col.f32.f16.f16.f32 "                 \
        "{%0,%1,%2,%3}, {%4,%5,%6,%7}, {%8,%9}, {%0,%1,%2,%3};\n"            \
        : "+f"(D0), "+f"(D1), "+f"(D2), "+f"(D3)                             \
        : "r"(A0), "r"(A1), "r"(A2), "r"(A3), "r"(B0), "r"(B1))

// ---------------------------------------------------------------------------
// Stage 1: Cayley. One block per (side, head), 256 threads.
// Chunked unroll (4 x 16): static reg indices, I$-resident code.
// Unpivoted GJ safe: symmetric part of I+A is I (SPD). End: X = R (fp16 out).
// ---------------------------------------------------------------------------
__global__ __launch_bounds__(256) void cayley_kernel(
    const float* __restrict__ pL, const float* __restrict__ pR)
{
    const int side = blockIdx.x >> 5;
    const int h    = blockIdx.x & 31;
    const float* p = (side ? pR : pL) + h * DIM * DIM;

    const int tid = threadIdx.x;
    const int r   = tid >> 2;
    const int q   = tid & 3;
    const int cb  = q * 16;

    __shared__ float rowM[DIM], rowX[DIM], colM[DIM];

    float m[16], x[16];
    #pragma unroll
    for (int j = 0; j < 16; j++) {
        int c = cb + j;
        float a = 0.5f * (p[r * DIM + c] - p[c * DIM + r]);
        float id = (r == c) ? 1.0f : 0.0f;
        m[j] = id + a;
        x[j] = id - a;
    }
    __syncthreads();

    #pragma unroll 1
    for (int chunk = 0; chunk < 4; chunk++) {
        #pragma unroll
        for (int kk = 0; kk < 16; kk++) {
            const int k = (chunk << 4) + kk;
            if (r == k) {
                #pragma unroll
                for (int j = 0; j < 16; j++) { rowM[cb + j] = m[j]; rowX[cb + j] = x[j]; }
            }
            if (chunk == q) colM[r] = m[kk];     // kk literal -> static index
            __syncthreads();

            const float invp = 1.0f / rowM[k];
            if (r == k) {
                #pragma unroll
                for (int j = 0; j < 16; j++) { m[j] *= invp; x[j] *= invp; }
            } else {
                const float f = colM[r] * invp;
                #pragma unroll
                for (int j = 0; j < 16; j++) {
                    m[j] -= f * rowM[cb + j];
                    x[j] -= f * rowX[cb + j];
                }
            }
            __syncthreads();
        }
    }

    if (side == 0) {
        __half* dst = g_R1h + h * DIM * DIM;
        #pragma unroll
        for (int j = 0; j < 16; j++) dst[r * DIM + cb + j] = __float2half_rn(x[j]);
    } else {
        __half* dst = g_R2Th + h * DIM * DIM;
        #pragma unroll
        for (int j = 0; j < 16; j++) dst[(cb + j) * DIM + r] = __float2half_rn(x[j]);
    }

    // Release the PDL edge as early as possible.
    cudaTriggerProgrammaticLaunchCompletion();
}

// ---------------------------------------------------------------------------
// Stage 2: 4096 blocks (head-major), 128 threads = 2 warp-pairs, 2 passes
// -> 4 batches/block sharing one R staging. Warp w2 owns j in [w2*32,+32).
// ---------------------------------------------------------------------------
__global__ __launch_bounds__(128, 4) void bilat_kernel(
    const float* __restrict__ wkv, float* __restrict__ out)
{
    extern __shared__ char smem[];
    __half* sR1h  = reinterpret_cast<__half*>(smem);            // [i][r]
    __half* sR2Th = reinterpret_cast<__half*>(smem) + MATH;     // [j][l]
    float*  sWbase = reinterpret_cast<float*>(smem + 2 * MATH * 2);

    const int blk  = blockIdx.x;
    const int head = blk >> 7;           // head-major: R matrices L2-hot
    const int g    = blk & 127;

    const int tid    = threadIdx.x;
    const int lane   = tid & 31;
    const int warp   = tid >> 5;
    const int pairid = warp >> 1;        // 0,1
    const int w2     = warp & 1;
    const int grp    = lane >> 2;        // 0..7
    const int tig    = lane & 3;         // 0..3
    const int base   = w2 * 32;          // this warp's j-range
    const int tp     = tid & 63;

    float* sW = sWbase + pairid * MATW;  // W natural [r][l], f32

    // ---- cp.async (cg): W for pass 0 — independent of cayley output ----
    {
        const int b0 = g * 4 + pairid;
        const float4* wsrc = reinterpret_cast<const float4*>(wkv)
                           + (size_t)(b0 * NUM_HEADS + head) * 1024;
        #pragma unroll 4
        for (int ci = tp; ci < 1024; ci += 64) {
            int r = ci >> 4, c4 = (ci & 15) << 2;
            cp16_cg(&sW[r * PITCH + c4], wsrc + ci);
        }
    }
    CP_COMMIT();

    // ---- wait for cayley's R writes (PDL dependency) ----
    cudaGridDependencySynchronize();

    // ---- cp.async (ca): R1 + R2T (fp16; 8 halfs = 16B per chunk) ----
    {
        const float4* r1g = reinterpret_cast<const float4*>(g_R1h  + (size_t)head * 4096);
        const float4* r2g = reinterpret_cast<const float4*>(g_R2Th + (size_t)head * 4096);
        #pragma unroll 4
        for (int ci = tid; ci < 512; ci += 128) {
            int r = ci >> 3, c8 = (ci & 7) << 3;          // 8 chunks/row
            cp16_ca(&sR1h [r * PITCHH + c8], r1g + ci);
            cp16_ca(&sR2Th[r * PITCHH + c8], r2g + ci);
        }
    }
    CP_COMMIT();

    CP_WAIT0();
    __syncthreads();

    #pragma unroll 1
    for (int pass = 0; pass < 2; pass++) {
        const int b = g * 4 + pass * 2 + pairid;

        CP_WAIT0();            // this pass's W chunks (own thread) done
        pbar(1 + pairid);      // all pair threads' chunks visible

        // ---- GEMM1: Tt = R2T @ W^T  (fp16 k16) ----
        // acc1[mt][nt]: rows j = base+mt*16+grp(+8), cols r = nt*8+2tig(+1)
        float acc1[2][8][4];
        #pragma unroll
        for (int mt = 0; mt < 2; mt++)
            #pragma unroll
            for (int nt = 0; nt < 8; nt++)
                { acc1[mt][nt][0]=0.f; acc1[mt][nt][1]=0.f; acc1[mt][nt][2]=0.f; acc1[mt][nt][3]=0.f; }

        #pragma unroll
        for (int kk = 0; kk < 4; kk++) {
            const int l0 = kk * 16 + 2 * tig;
            uint32_t a[2][4];
            #pragma unroll
            for (int mt = 0; mt < 2; mt++) {
                const int j0 = base + mt * 16 + grp;
                a[mt][0] = *reinterpret_cast<const uint32_t*>(&sR2Th[ j0      * PITCHH + l0    ]);
                a[mt][1] = *reinterpret_cast<const uint32_t*>(&sR2Th[(j0 + 8) * PITCHH + l0    ]);
                a[mt][2] = *reinterpret_cast<const uint32_t*>(&sR2Th[ j0      * PITCHH + l0 + 8]);
                a[mt][3] = *reinterpret_cast<const uint32_t*>(&sR2Th[(j0 + 8) * PITCHH + l0 + 8]);
            }
            #pragma unroll
            for (int nt = 0; nt < 8; nt++) {
                const int r = nt * 8 + grp;
                float2 w0 = *reinterpret_cast<const float2*>(&sW[r * PITCH + l0    ]);
                float2 w1 = *reinterpret_cast<const float2*>(&sW[r * PITCH + l0 + 8]);
                const uint32_t b0 = pack_h2(w0.x, w0.y);
                const uint32_t b1 = pack_h2(w1.x, w1.y);
                #pragma unroll
                for (int mt = 0; mt < 2; mt++)
                    MMA_F16(acc1[mt][nt][0], acc1[mt][nt][1], acc1[mt][nt][2], acc1[mt][nt][3],
                            a[mt][0], a[mt][1], a[mt][2], a[mt][3], b0, b1);
            }
        }
        pbar(1 + pairid);      // pair done reading W -> sW free

        // ---- prefetch next pass's W: overlaps GEMM2 + epilogue ----
        if (pass == 0) {
            const int bn = b + 2;
            const float4* wsrc = reinterpret_cast<const float4*>(wkv)
                               + (size_t)(bn * NUM_HEADS + head) * 1024;
            #pragma unroll 4
            for (int ci = tp; ci < 1024; ci += 64) {
                int r = ci >> 4, c4 = (ci & 15) << 2;
                cp16_cg(&sW[r * PITCH + c4], wsrc + ci);
            }
            CP_COMMIT();
        }

        // ---- pack Tt to fp16 (acc1 dies here; 32 regs live on) ----
        // acc1h[mt][nt][h]: h=0 -> row j0, h=1 -> row j0+8; f16x2 of (r=2tig,2tig+1)
        uint32_t acc1h[2][8][2];
        #pragma unroll
        for (int mt = 0; mt < 2; mt++)
            #pragma unroll
            for (int nt = 0; nt < 8; nt++) {
                acc1h[mt][nt][0] = pack_h2(acc1[mt][nt][0], acc1[mt][nt][1]);
                acc1h[mt][nt][1] = pack_h2(acc1[mt][nt][2], acc1[mt][nt][3]);
            }

        // ---- GEMM2: out = R1 @ T  (A = fp16 R1, B = Tt from registers) ----
        // acc2[mt][nt]: rows i = mt*16+grp(+8), cols j = base+nt*8+2tig(+1)
        float acc2[4][4][4];
        #pragma unroll
        for (int mt = 0; mt < 4; mt++)
            #pragma unroll
            for (int nt = 0; nt < 4; nt++)
                { acc2[mt][nt][0]=0.f; acc2[mt][nt][1]=0.f; acc2[mt][nt][2]=0.f; acc2[mt][nt][3]=0.f; }

        #pragma unroll
        for (int kk = 0; kk < 4; kk++) {
            const int r0 = kk * 16 + 2 * tig;
            uint32_t a[4][4];
            #pragma unroll
            for (int mt = 0; mt < 4; mt++) {
                const int i0 = mt * 16 + grp;
                a[mt][0] = *reinterpret_cast<const uint32_t*>(&sR1h[ i0      * PITCHH + r0    ]);
                a[mt][1] = *reinterpret_cast<const uint32_t*>(&sR1h[(i0 + 8) * PITCHH + r0    ]);
                a[mt][2] = *reinterpret_cast<const uint32_t*>(&sR1h[ i0      * PITCHH + r0 + 8]);
                a[mt][3] = *reinterpret_cast<const uint32_t*>(&sR1h[(i0 + 8) * PITCHH + r0 + 8]);
            }
            #pragma unroll
            for (int nt = 0; nt < 4; nt++) {
                // B frag: Tt[j = base+nt*8+grp][r-block kk] from registers
                const uint32_t b0 = acc1h[nt >> 1][2 * kk    ][nt & 1];
                const uint32_t b1 = acc1h[nt >> 1][2 * kk + 1][nt & 1];
                #pragma unroll
                for (int mt = 0; mt < 4; mt++)
                    MMA_F16(acc2[mt][nt][0], acc2[mt][nt][1], acc2[mt][nt][2], acc2[mt][nt][3],
                            a[mt][0], a[mt][1], a[mt][2], a[mt][3], b0, b1);
            }
        }

        // ---- epilogue: coalesced float2 stores ----
        float* dst = out + (size_t)(b * NUM_HEADS + head) * (DIM * DIM);
        #pragma unroll
        for (int mt = 0; mt < 4; mt++) {
            const int i0 = mt * 16 + grp;
            #pragma unroll
            for (int nt = 0; nt < 4; nt++) {
                const int col = base + nt * 8 + 2 * tig;
                *reinterpret_cast<float2*>(dst +  i0      * DIM + col) =
                    make_float2(acc2[mt][nt][0], acc2[mt][nt][1]);
                *reinterpret_cast<float2*>(dst + (i0 + 8) * DIM + col) =
                    make_float2(acc2[mt][nt][2], acc2[mt][nt][3]);
            }
        }
    }
}

// ---------------------------------------------------------------------------
extern "C" void kernel_launch(void* const* d_in, const int* in_sizes, int n_in,
                              void* d_out, int out_size)
{
    const float* wkv = (const float*)d_in[0];
    const float* pL  = (const float*)d_in[1];
    const float* pR  = (const float*)d_in[2];
    float* out       = (float*)d_out;

    // Unconditional; immediate host-side API, idempotent, capture-safe.
    cudaFuncSetAttribute(bilat_kernel,
                         cudaFuncAttributeMaxDynamicSharedMemorySize,
                         SMEM_TOTAL_BYTES);

    cayley_kernel<<<2 * NUM_HEADS, 256>>>(pL, pR);

    // PDL launch: bilat starts while cayley runs; dependency resolved by
    // cudaGridDependencySynchronize() inside bilat before it reads g_R*.
    cudaLaunchConfig_t cfg = {};
    cfg.gridDim          = dim3(NUM_HEADS * 128, 1, 1);
    cfg.blockDim         = dim3(128, 1, 1);
    cfg.dynamicSmemBytes = SMEM_TOTAL_BYTES;
    cfg.stream           = 0;
    cudaLaunchAttribute attr[1];
    attr[0].id = cudaLaunchAttributeProgrammaticStreamSerialization;
    attr[0].val.programmaticStreamSerializationAllowed = 1;
    cfg.attrs    = attr;
    cfg.numAttrs = 1;
    cudaLaunchKernelEx(&cfg, bilat_kernel, wkv, out);
}